// round 1
// baseline (speedup 1.0000x reference)
#include <cuda_runtime.h>
#include <cuda_bf16.h>
#include <math.h>

// Problem constants
#define NNODES 200000
#define NEDGES 600000
#define NGRAPHS 4000
#define IN_DIM 25
#define EDGE_DIM 11
#define HID 128
#define DEPTH 4
#define KMSG (HID + EDGE_DIM)   // 139
#define KUP  (2 * HID)          // 256
#define BN_EPS 1e-5f

// Scratch (static device globals; no runtime allocation)
__device__ float g_h[(size_t)NNODES * HID];     // node features
__device__ float g_aggr[(size_t)NNODES * HID];  // scatter-add target, then reused as "out"
__device__ float g_bnsum[HID];
__device__ float g_bnsq[HID];
__device__ float g_cnt[NGRAPHS];

// ---------------------------------------------------------------------------
// Input projection: h = lrelu(x @ W_in + b_in)   [N,25]@[25,128]
// blockDim=128 (one col per thread), 8 nodes per block
// ---------------------------------------------------------------------------
__global__ __launch_bounds__(128) void input_proj_kernel(
    const float* __restrict__ x, const float* __restrict__ W,
    const float* __restrict__ b)
{
    __shared__ float xs[8][IN_DIM];
    const int n0 = blockIdx.x * 8;
    const int c = threadIdx.x;

    for (int i = threadIdx.x; i < 8 * IN_DIM; i += 128) {
        int r = i / IN_DIM, k = i - r * IN_DIM;
        xs[r][k] = x[(size_t)(n0 + r) * IN_DIM + k];
    }
    __syncthreads();

    float wcol[IN_DIM];
#pragma unroll
    for (int k = 0; k < IN_DIM; k++) wcol[k] = W[k * HID + c];
    const float bias = b[c];

#pragma unroll
    for (int r = 0; r < 8; r++) {
        float acc = bias;
#pragma unroll
        for (int k = 0; k < IN_DIM; k++) acc = fmaf(xs[r][k], wcol[k], acc);
        g_h[(size_t)(n0 + r) * HID + c] = acc > 0.f ? acc : 0.1f * acc;
    }
}

// ---------------------------------------------------------------------------
// Zero aggr + BN accumulators (per layer)
// ---------------------------------------------------------------------------
__global__ void zero_layer_kernel()
{
    size_t idx = (size_t)blockIdx.x * blockDim.x + threadIdx.x;
    size_t stride = (size_t)gridDim.x * blockDim.x;
    for (size_t i = idx; i < (size_t)NNODES * HID; i += stride) g_aggr[i] = 0.f;
    if (blockIdx.x == 0 && threadIdx.x < HID) {
        g_bnsum[threadIdx.x] = 0.f;
        g_bnsq[threadIdx.x] = 0.f;
    }
}

// ---------------------------------------------------------------------------
// Edge message + scatter-add:
//   msg = lrelu(cat[h[src], edge_attr] @ W_msg + b_msg); atomicAdd into aggr[dst]
// 64 edges per block, 256 threads. W_msg (139x128) + edge tile in dynamic SMEM.
// Thread t: cols lane+32j (j=0..3), edges (t>>5)*8 .. +7  -> 32 accs
// ---------------------------------------------------------------------------
#define ETILE 64
#define ESTRIDE 140  // padded row stride for inputs (>=139, 16B-aligned)
#define EDGE_SMEM (KMSG * HID * 4 + ETILE * ESTRIDE * 4)

extern __shared__ float sm_dyn[];

__global__ __launch_bounds__(256) void edge_msg_kernel(
    const int* __restrict__ src, const int* __restrict__ dst,
    const float* __restrict__ eattr,
    const float* __restrict__ Wm, const float* __restrict__ bm)
{
    float* Ws = sm_dyn;                 // [139][128]
    float* ins = sm_dyn + KMSG * HID;   // [64][140]

    const int tid = threadIdx.x;
    const int lane = tid & 31;
    const int wid = tid >> 5;
    const int eb = blockIdx.x * ETILE;

    // Load W_msg tile (17792 floats) via float4
    {
        const float4* Wg4 = (const float4*)Wm;
        float4* Ws4 = (float4*)Ws;
        for (int i = tid; i < KMSG * HID / 4; i += 256) Ws4[i] = Wg4[i];
    }
    // Gather h[src] rows (128 floats each) via float4, one warp per row
    for (int e = wid; e < ETILE; e += 8) {
        int s = src[eb + e];
        float4 v = *(const float4*)(g_h + (size_t)s * HID + lane * 4);
        *(float4*)(ins + e * ESTRIDE + lane * 4) = v;
    }
    // edge_attr (11 floats per edge)
    for (int i = tid; i < ETILE * EDGE_DIM; i += 256) {
        int e = i / EDGE_DIM, k = i - e * EDGE_DIM;
        ins[e * ESTRIDE + HID + k] = eattr[(size_t)(eb + e) * EDGE_DIM + k];
    }
    __syncthreads();

    float acc[8][4];
#pragma unroll
    for (int e = 0; e < 8; e++)
#pragma unroll
        for (int j = 0; j < 4; j++) acc[e][j] = 0.f;

    const float* insrow = ins + (wid * 8) * ESTRIDE;
    for (int k = 0; k < KMSG; k++) {
        const float w0 = Ws[k * HID + lane];
        const float w1 = Ws[k * HID + lane + 32];
        const float w2 = Ws[k * HID + lane + 64];
        const float w3 = Ws[k * HID + lane + 96];
#pragma unroll
        for (int e = 0; e < 8; e++) {
            const float v = insrow[e * ESTRIDE + k];
            acc[e][0] = fmaf(v, w0, acc[e][0]);
            acc[e][1] = fmaf(v, w1, acc[e][1]);
            acc[e][2] = fmaf(v, w2, acc[e][2]);
            acc[e][3] = fmaf(v, w3, acc[e][3]);
        }
    }

    const float b0 = bm[lane], b1 = bm[lane + 32], b2 = bm[lane + 64], b3 = bm[lane + 96];
#pragma unroll
    for (int e = 0; e < 8; e++) {
        const int d = dst[eb + wid * 8 + e];
        float* arow = g_aggr + (size_t)d * HID;
        float z0 = acc[e][0] + b0; z0 = z0 > 0.f ? z0 : 0.1f * z0;
        float z1 = acc[e][1] + b1; z1 = z1 > 0.f ? z1 : 0.1f * z1;
        float z2 = acc[e][2] + b2; z2 = z2 > 0.f ? z2 : 0.1f * z2;
        float z3 = acc[e][3] + b3; z3 = z3 > 0.f ? z3 : 0.1f * z3;
        atomicAdd(arow + lane, z0);
        atomicAdd(arow + lane + 32, z1);
        atomicAdd(arow + lane + 64, z2);
        atomicAdd(arow + lane + 96, z3);
    }
}

// ---------------------------------------------------------------------------
// Update: out = relu(cat[aggr, h] @ W_up + b_up)  (lrelu then relu == relu)
// Writes out in-place over g_aggr. Also accumulates BN sum/sumsq.
// 32 nodes per block, 256 threads. W_up (256x128) + node tile in SMEM.
// Thread t: cols lane+32j, rows (t>>5)*4 .. +3
// ---------------------------------------------------------------------------
#define NTILE 32
#define UPD_SMEM (KUP * HID * 4 + NTILE * KUP * 4)

__global__ __launch_bounds__(256) void update_kernel(
    const float* __restrict__ Wu, const float* __restrict__ bu)
{
    float* Ws = sm_dyn;                // [256][128]
    float* ins = sm_dyn + KUP * HID;   // [32][256]
    __shared__ float s_sum[HID];
    __shared__ float s_sq[HID];

    const int tid = threadIdx.x;
    const int lane = tid & 31;
    const int wid = tid >> 5;
    const int n0 = blockIdx.x * NTILE;

    if (tid < HID) { s_sum[tid] = 0.f; s_sq[tid] = 0.f; }

    // Load W_up (32768 floats) via float4
    {
        const float4* Wg4 = (const float4*)Wu;
        float4* Ws4 = (float4*)Ws;
        for (int i = tid; i < KUP * HID / 4; i += 256) Ws4[i] = Wg4[i];
    }
    // Input tile: [32 rows][256] = cat[aggr row, h row], float4 chunks
    for (int i = tid; i < NTILE * (KUP / 4); i += 256) {
        int r = i / (KUP / 4), q = i - r * (KUP / 4);  // q = float4 index 0..63
        const float* srcp = (q < 32) ? (g_aggr + (size_t)(n0 + r) * HID + q * 4)
                                     : (g_h + (size_t)(n0 + r) * HID + (q - 32) * 4);
        *(float4*)(ins + r * KUP + q * 4) = *(const float4*)srcp;
    }
    __syncthreads();

    float acc[4][4];
#pragma unroll
    for (int r = 0; r < 4; r++)
#pragma unroll
        for (int j = 0; j < 4; j++) acc[r][j] = 0.f;

    const float* insrow = ins + (wid * 4) * KUP;
    for (int k = 0; k < KUP; k++) {
        const float w0 = Ws[k * HID + lane];
        const float w1 = Ws[k * HID + lane + 32];
        const float w2 = Ws[k * HID + lane + 64];
        const float w3 = Ws[k * HID + lane + 96];
#pragma unroll
        for (int r = 0; r < 4; r++) {
            const float v = insrow[r * KUP + k];
            acc[r][0] = fmaf(v, w0, acc[r][0]);
            acc[r][1] = fmaf(v, w1, acc[r][1]);
            acc[r][2] = fmaf(v, w2, acc[r][2]);
            acc[r][3] = fmaf(v, w3, acc[r][3]);
        }
    }

    const float b0 = bu[lane], b1 = bu[lane + 32], b2 = bu[lane + 64], b3 = bu[lane + 96];
    float psum[4] = {0.f, 0.f, 0.f, 0.f};
    float psq[4] = {0.f, 0.f, 0.f, 0.f};
#pragma unroll
    for (int r = 0; r < 4; r++) {
        const int n = n0 + wid * 4 + r;
        float* orow = g_aggr + (size_t)n * HID;
        float z0 = fmaxf(acc[r][0] + b0, 0.f);
        float z1 = fmaxf(acc[r][1] + b1, 0.f);
        float z2 = fmaxf(acc[r][2] + b2, 0.f);
        float z3 = fmaxf(acc[r][3] + b3, 0.f);
        orow[lane] = z0; orow[lane + 32] = z1; orow[lane + 64] = z2; orow[lane + 96] = z3;
        psum[0] += z0; psum[1] += z1; psum[2] += z2; psum[3] += z3;
        psq[0] += z0 * z0; psq[1] += z1 * z1; psq[2] += z2 * z2; psq[3] += z3 * z3;
    }
    __syncthreads();  // s_sum/s_sq init visible (init was before first sync anyway)
#pragma unroll
    for (int j = 0; j < 4; j++) {
        atomicAdd(&s_sum[lane + 32 * j], psum[j]);
        atomicAdd(&s_sq[lane + 32 * j], psq[j]);
    }
    __syncthreads();
    if (tid < HID) {
        atomicAdd(&g_bnsum[tid], s_sum[tid]);
        atomicAdd(&g_bnsq[tid], s_sq[tid]);
    }
}

// ---------------------------------------------------------------------------
// BN normalize: h = gamma*(out - mu)*rsqrt(var+eps) + beta  (out lives in g_aggr)
// ---------------------------------------------------------------------------
__global__ void bn_norm_kernel(const float* __restrict__ gamma,
                               const float* __restrict__ beta)
{
    __shared__ float sc[HID], off[HID];
    if (threadIdx.x < HID) {
        int c = threadIdx.x;
        float mu = g_bnsum[c] * (1.f / NNODES);
        float var = g_bnsq[c] * (1.f / NNODES) - mu * mu;
        var = fmaxf(var, 0.f);
        float s = gamma[c] * rsqrtf(var + BN_EPS);
        sc[c] = s;
        off[c] = beta[c] - mu * s;
    }
    __syncthreads();
    size_t idx = (size_t)blockIdx.x * blockDim.x + threadIdx.x;
    size_t stride = (size_t)gridDim.x * blockDim.x;
    for (size_t i = idx; i < (size_t)NNODES * HID; i += stride) {
        int c = (int)(i & (HID - 1));
        g_h[i] = fmaf(g_aggr[i], sc[c], off[c]);
    }
}

// ---------------------------------------------------------------------------
// Pooling
// ---------------------------------------------------------------------------
__global__ void zero_pool_kernel(float* __restrict__ out)
{
    size_t idx = (size_t)blockIdx.x * blockDim.x + threadIdx.x;
    size_t stride = (size_t)gridDim.x * blockDim.x;
    for (size_t i = idx; i < (size_t)NGRAPHS * HID; i += stride) out[i] = 0.f;
    for (size_t i = idx; i < NGRAPHS; i += stride) g_cnt[i] = 0.f;
}

#define PNODES 16
__global__ __launch_bounds__(128) void pool_kernel(
    const int* __restrict__ batch, float* __restrict__ out)
{
    const int n0 = blockIdx.x * PNODES;
    const int c = threadIdx.x;
    for (int r = 0; r < PNODES; r++) {
        const int n = n0 + r;
        const int g = batch[n];
        atomicAdd(&out[(size_t)g * HID + c], g_h[(size_t)n * HID + c]);
        if (c == 0) atomicAdd(&g_cnt[g], 1.f);
    }
}

__global__ void pool_div_kernel(float* __restrict__ out)
{
    size_t i = (size_t)blockIdx.x * blockDim.x + threadIdx.x;
    if (i < (size_t)NGRAPHS * HID) {
        int g = (int)(i >> 7);
        out[i] /= fmaxf(g_cnt[g], 1.f);
    }
}

// ---------------------------------------------------------------------------
// Launch
// ---------------------------------------------------------------------------
extern "C" void kernel_launch(void* const* d_in, const int* in_sizes, int n_in,
                              void* d_out, int out_size)
{
    const float* x      = (const float*)d_in[0];
    const int*   eidx   = (const int*)d_in[1];     // [2, E]
    const float* eattr  = (const float*)d_in[2];
    const int*   batch  = (const int*)d_in[3];
    const float* W_in   = (const float*)d_in[4];
    const float* b_in   = (const float*)d_in[5];
    const float* W_msg  = (const float*)d_in[6];   // [4,139,128]
    const float* b_msg  = (const float*)d_in[7];   // [4,128]
    const float* W_up   = (const float*)d_in[8];   // [4,256,128]
    const float* b_up   = (const float*)d_in[9];   // [4,128]
    const float* gamma  = (const float*)d_in[10];
    const float* beta   = (const float*)d_in[11];
    float* out = (float*)d_out;

    const int* src = eidx;
    const int* dst = eidx + NEDGES;

    cudaFuncSetAttribute(edge_msg_kernel, cudaFuncAttributeMaxDynamicSharedMemorySize, EDGE_SMEM);
    cudaFuncSetAttribute(update_kernel, cudaFuncAttributeMaxDynamicSharedMemorySize, UPD_SMEM);

    input_proj_kernel<<<NNODES / 8, 128>>>(x, W_in, b_in);

    for (int i = 0; i < DEPTH; i++) {
        zero_layer_kernel<<<2048, 256>>>();
        edge_msg_kernel<<<NEDGES / ETILE, 256, EDGE_SMEM>>>(
            src, dst, eattr, W_msg + (size_t)i * KMSG * HID, b_msg + i * HID);
        update_kernel<<<NNODES / NTILE, 256, UPD_SMEM>>>(
            W_up + (size_t)i * KUP * HID, b_up + i * HID);
        bn_norm_kernel<<<2048, 256>>>(gamma + i * HID, beta + i * HID);
    }

    zero_pool_kernel<<<512, 256>>>(out);
    pool_kernel<<<NNODES / PNODES, 128>>>(batch, out);
    pool_div_kernel<<<(NGRAPHS * HID + 255) / 256, 256>>>(out);
}